// round 16
// baseline (speedup 1.0000x reference)
#include <cuda_runtime.h>
#include <cuda_fp16.h>
#include <cstdint>
#include <cstddef>

// Problem: B=4096, P=10, LD=TD=512, DIN=2048, BP=40960
// out = [logits 4096x10][best_lane 4096x512][best_nghl 4096x512][best_ngh 4096x512]
// compute_103 PTX -> legacy mma.sync.m16n8k16 + cp.async only.
// ctx@W1 = agent@W1a (x10 smaller) + [lane|nghl|ngh]@W1bcd.
// R16: f32->f16 A-conversion fused INTO gemm1 via cp.async-staged f32 +
// pipelined in-SMEM convert. Unlike R5 (sync LDG) and R7 (split commit groups
// killed pipeline depth), each stage is ONE commit group {A_f32, B_f16} and
// wait(1) guarantees stage c+1 complete -> convert one chunk ahead of MMA.
// prep_rows deleted; replaced by a tiny gather-only kernel.

__device__ __align__(16) __half g_W1t[512 * 2048];       // W1^T fp16 [n][k]
__device__ __align__(16) __half g_agenth[4096u * 512];   // agent fp16
__device__ __align__(16) float  g_agw[4096u * 512];      // agent@W1a + b1 (fp32)
__device__ __align__(16) __half g_embh[40960u * 512];    // relu(...) fp16 (= [4096][5120])
__device__ __align__(16) __half g_W2h[16 * 5120];        // W2^T padded fp16 [n16][k5120]

#define SW128(o) ((o) ^ (((o) >> 3) & 0x70))

__device__ __forceinline__ uint32_t smem_u32(const void* p) {
    uint32_t a;
    asm("{ .reg .u64 t; cvta.to.shared.u64 t, %1; cvt.u32.u64 %0, t; }" : "=r"(a) : "l"(p));
    return a;
}
__device__ __forceinline__ uint32_t pack_h2(float a, float b) {
    __half2 h = __floats2half2_rn(a, b);
    return *reinterpret_cast<uint32_t*>(&h);
}

#define CP16(dst, src) \
    asm volatile("cp.async.cg.shared.global [%0], [%1], 16;" :: "r"(dst), "l"(src) : "memory")
#define CP_COMMIT() asm volatile("cp.async.commit_group;" ::: "memory")
#define CP_WAIT(n)  asm volatile("cp.async.wait_group %0;" :: "n"(n) : "memory")

#define LDSM_X4(r, addr)                                                          \
    asm volatile("ldmatrix.sync.aligned.m8n8.x4.shared.b16 {%0,%1,%2,%3}, [%4];"  \
        : "=r"((r)[0]), "=r"((r)[1]), "=r"((r)[2]), "=r"((r)[3]) : "r"(addr))

#define MMA16816(d, a, b0, b1)                                                    \
    asm volatile("mma.sync.aligned.m16n8k16.row.col.f32.f16.f16.f32 "             \
        "{%0,%1,%2,%3}, {%4,%5,%6,%7}, {%8,%9}, {%0,%1,%2,%3};"                    \
        : "+f"((d)[0]), "+f"((d)[1]), "+f"((d)[2]), "+f"((d)[3])                   \
        : "r"((a)[0]), "r"((a)[1]), "r"((a)[2]), "r"((a)[3]), "r"(b0), "r"(b1))

// ---------------- Kernel 1: W1[2048,512] f32 -> W1t[512][2048] f16 ----------------
__global__ void w1t_kernel(const float* __restrict__ W1) {
    __shared__ float t[32][33];
    int kk = blockIdx.x * 32, nn = blockIdx.y * 32;
    int tx = threadIdx.x, ty = threadIdx.y;  // 32 x 8
#pragma unroll
    for (int q = 0; q < 4; q++)
        t[ty + 8 * q][tx] = W1[(size_t)(kk + ty + 8 * q) * 512 + nn + tx];
    __syncthreads();
#pragma unroll
    for (int q = 0; q < 4; q++)
        g_W1t[(size_t)(nn + ty + 8 * q) * 2048 + kk + tx] = __float2half(t[tx][ty + 8 * q]);
}

// ---------------- Kernel 2: agent cvt + W2 cvt + logits init (merged) --------------
__global__ void __launch_bounds__(256) prep2_kernel(const float* __restrict__ agent,
                                                    const float* __restrict__ W2,
                                                    const float* __restrict__ b2,
                                                    float* __restrict__ logits) {
    int blk = blockIdx.x;
    if (blk < 2048) {
        int idx = blk * 256 + threadIdx.x;          // 524288 float4s
        float4 v = __ldg((const float4*)agent + idx);
        uint2 o = { pack_h2(v.x, v.y), pack_h2(v.z, v.w) };
        *(uint2*)(g_agenth + (size_t)idx * 4) = o;
    } else {
        int idx = (blk - 2048) * 256 + threadIdx.x; // 122880
        if (idx < 81920) {
            int n = idx / 5120, k = idx % 5120;
            g_W2h[idx] = __float2half(n < 10 ? W2[(size_t)k * 10 + n] : 0.0f);
        } else {
            int j = idx - 81920;                    // 40960
            logits[j] = __ldg(b2 + j % 10);
        }
    }
}

// ---------------- Kernel 3: gather best_* by one-hot label (small) ----------------
__global__ void __launch_bounds__(128) gather_kernel(
    const float* __restrict__ lanec, const float* __restrict__ nghl,
    const float* __restrict__ ngh,   const int* __restrict__ label,
    float* __restrict__ out)
{
    int b = blockIdx.x, t = threadIdx.x;
    __shared__ int sidx;
    if (t < 10 && __ldg(label + b * 10 + t) == 1) sidx = t;
    __syncthreads();
    size_t src = ((size_t)b * 10 + sidx) * 512 + t * 4;
    size_t dst = (size_t)b * 512 + t * 4;
    *(float4*)(out + 40960 + dst)           = __ldg((const float4*)(lanec + src));
    *(float4*)(out + 40960 + 2097152 + dst) = __ldg((const float4*)(nghl + src));
    *(float4*)(out + 40960 + 4194304 + dst) = __ldg((const float4*)(ngh + src));
}

// ---------------- Kernel 4: agemm  g_agw = agent@W1a + b1 (fp32) ----------------
#define AG_STAGES  4
#define AG_A_STAGE 16384
#define AG_B_STAGE 16384
#define AG_SMEM    (AG_STAGES * (AG_A_STAGE + AG_B_STAGE))   // 131072

__global__ void __launch_bounds__(256, 1) agemm_kernel(const float* __restrict__ b1) {
    extern __shared__ char sm[];
    const uint32_t sA = smem_u32(sm);
    const uint32_t sB = sA + AG_STAGES * AG_A_STAGE;
    const int t = threadIdx.x;
    const int n0 = blockIdx.x * 128;
    const int m0 = blockIdx.y * 128;
    const __half* gA = g_agenth + (size_t)m0 * 512;
    const __half* gB = g_W1t + (size_t)n0 * 2048;   // k offset 0..511

    const int lrow = t >> 3, lcu = t & 7;
    const int warp = t >> 5, ln = t & 31;
    const int wm = warp & 3, wn = warp >> 2;
    const int a_row = (ln & 7) + ((ln >> 3) & 1) * 8;
    const int a_kb  = (ln >> 4) << 4;
    const uint32_t aBase = (uint32_t)(wm * 32 + a_row) * 128 + a_kb;
    const int b_row = (ln & 7) + ((ln >> 4) << 3);
    const int b_kb  = ((ln >> 3) & 1) << 4;
    const uint32_t bBase = (uint32_t)(wn * 64 + b_row) * 128 + b_kb;

    float d[2][8][4];
#pragma unroll
    for (int mf = 0; mf < 2; mf++)
#pragma unroll
        for (int nf = 0; nf < 8; nf++)
#pragma unroll
            for (int q = 0; q < 4; q++) d[mf][nf][q] = 0.0f;

    auto load_stage = [&](int c, int slot) {
        const int k0 = c * 64;
#pragma unroll
        for (int i = 0; i < 4; i++) {
            int row = lrow + 32 * i;
            CP16(sA + slot * AG_A_STAGE + SW128(row * 128 + lcu * 16),
                 gA + (size_t)row * 512 + k0 + lcu * 8);
            CP16(sB + slot * AG_B_STAGE + SW128(row * 128 + lcu * 16),
                 gB + (size_t)row * 2048 + k0 + lcu * 8);
        }
    };

#pragma unroll
    for (int s = 0; s < AG_STAGES - 1; s++) { load_stage(s, s); CP_COMMIT(); }

    for (int c = 0; c < 8; c++) {
        CP_WAIT(2);
        __syncthreads();
        if (c + AG_STAGES - 1 < 8) load_stage(c + AG_STAGES - 1, (c + AG_STAGES - 1) & 3);
        CP_COMMIT();
        const uint32_t slotA = sA + (c & 3) * AG_A_STAGE;
        const uint32_t slotB = sB + (c & 3) * AG_B_STAGE;
#pragma unroll
        for (int s = 0; s < 4; s++) {
            uint32_t a[2][4], bb[4][4];
#pragma unroll
            for (int mf = 0; mf < 2; mf++)
                LDSM_X4(a[mf], slotA + SW128(aBase + mf * 2048 + s * 32));
#pragma unroll
            for (int nb = 0; nb < 4; nb++)
                LDSM_X4(bb[nb], slotB + SW128(bBase + nb * 2048 + s * 32));
#pragma unroll
            for (int mf = 0; mf < 2; mf++)
#pragma unroll
                for (int nf = 0; nf < 8; nf++) {
                    const int nb = nf >> 1, h = (nf & 1) * 2;
                    MMA16816(d[mf][nf], a[mf], bb[nb][h], bb[nb][h + 1]);
                }
        }
    }
    CP_WAIT(0);

    const int gid = ln >> 2, tc = (ln & 3) * 2;
#pragma unroll
    for (int nf = 0; nf < 8; nf++) {
        const int col = n0 + wn * 64 + nf * 8 + tc;
        float2 bv = __ldg((const float2*)(b1 + col));
#pragma unroll
        for (int mf = 0; mf < 2; mf++) {
            const int r0 = m0 + wm * 32 + mf * 16 + gid;
            float* dd = d[mf][nf];
            float2 s0 = { dd[0] + bv.x, dd[1] + bv.y };
            float2 s1 = { dd[2] + bv.x, dd[3] + bv.y };
            *(float2*)(g_agw + (size_t)r0 * 512 + col) = s0;
            *(float2*)(g_agw + (size_t)(r0 + 8) * 512 + col) = s1;
        }
    }
}

// ---------------- Kernel 5: GEMM1 fused: emb = relu(agw[b] + cvt(A_f32)@W1bcd) -----
// 128m x 256n, 512 threads. A: f32 cp.async (3-slot) -> pipelined SMEM convert
// (2 f16 bufs). B: f16 cp.async (3-slot). ONE commit group per stage {A,B}.
#define AF32_SZ  32768                     // 128 rows x 256B f32
#define BQ_SZ    32768                     // 256 rows x 128B f16
#define AF16_SZ  16384                     // 128 rows x 128B f16
#define SM_AF32  0
#define SM_BQ    (3 * AF32_SZ)             // 98304
#define SM_AF16  (SM_BQ + 3 * BQ_SZ)       // 196608
#define G1_SMEM  (SM_AF16 + 2 * AF16_SZ)   // 229376

__global__ void __launch_bounds__(512, 1) gemm1_kernel(
    const float* __restrict__ lanec, const float* __restrict__ nghl,
    const float* __restrict__ ngh)
{
    extern __shared__ char sm[];
    const uint32_t smb = smem_u32(sm);
    const int t = threadIdx.x;
    const int n0 = blockIdx.x * 256;
    const int m0 = blockIdx.y * 128;
    const __half* gB = g_W1t + (size_t)n0 * 2048 + 512;  // k range 512..2048

    // B cp.async addressing (512 threads: lrow 0..63)
    const int lrow = t >> 3, lcu = t & 7;
    // A f32 addressing: 4 threads per row, 64B (4x16B) each
    const int ar = t >> 2, aseg = t & 3;

    const int warp = t >> 5, ln = t & 31;  // warp 0..15
    const int wm = warp & 3, wn = warp >> 2;
    const int a_row = (ln & 7) + ((ln >> 3) & 1) * 8;
    const int a_kb  = (ln >> 4) << 4;
    const uint32_t aBase = (uint32_t)(wm * 32 + a_row) * 128 + a_kb;
    const int b_row = (ln & 7) + ((ln >> 4) << 3);
    const int b_kb  = ((ln >> 3) & 1) << 4;
    const uint32_t bBase = (uint32_t)(wn * 64 + b_row) * 128 + b_kb;

    float d[2][8][4];
#pragma unroll
    for (int mf = 0; mf < 2; mf++)
#pragma unroll
        for (int nf = 0; nf < 8; nf++)
#pragma unroll
            for (int q = 0; q < 4; q++) d[mf][nf][q] = 0.0f;

    auto load_stage = [&](int c, int slot) {
        const float* gA = (c < 8) ? lanec : (c < 16) ? nghl : ngh;
        const float* asrc = gA + (size_t)(m0 + ar) * 512 + ((c & 7) << 6) + aseg * 16;
        uint32_t adst = smb + SM_AF32 + slot * AF32_SZ + ar * 256 + aseg * 64;
#pragma unroll
        for (int i = 0; i < 4; i++)
            CP16(adst + i * 16, asrc + i * 4);
        const int kb0 = c * 64;
#pragma unroll
        for (int i = 0; i < 4; i++) {
            int row = lrow + 64 * i;
            CP16(smb + SM_BQ + slot * BQ_SZ + SW128(row * 128 + lcu * 16),
                 gB + (size_t)row * 2048 + kb0 + lcu * 8);
        }
    };
    auto cvtA = [&](int c) {
        const char* src = sm + SM_AF32 + (c % 3) * AF32_SZ + ar * 256 + aseg * 64;
        char* dst = sm + SM_AF16 + (c & 1) * AF16_SZ;
        const int abase = ar * 128 + aseg * 32;   // f16 byte offset
        float4 v0 = *(const float4*)(src);
        float4 v1 = *(const float4*)(src + 16);
        float4 v2 = *(const float4*)(src + 32);
        float4 v3 = *(const float4*)(src + 48);
        uint4 o0, o1;
        o0.x = pack_h2(v0.x, v0.y); o0.y = pack_h2(v0.z, v0.w);
        o0.z = pack_h2(v1.x, v1.y); o0.w = pack_h2(v1.z, v1.w);
        o1.x = pack_h2(v2.x, v2.y); o1.y = pack_h2(v2.z, v2.w);
        o1.z = pack_h2(v3.x, v3.y); o1.w = pack_h2(v3.z, v3.w);
        *(uint4*)(dst + SW128(abase))      = o0;
        *(uint4*)(dst + SW128(abase + 16)) = o1;
    };

    // prologue: stages 0,1 in flight (one group each)
    load_stage(0, 0); CP_COMMIT();
    load_stage(1, 1); CP_COMMIT();
    CP_WAIT(1);                            // stage 0 complete
    __syncthreads();                       // visibility of stage 0 across threads
    cvtA(0);
    __syncthreads();                       // f16 buf 0 visible

    for (int c = 0; c < 24; c++) {
        if (c + 2 < 24) { load_stage(c + 2, (c + 2) % 3); CP_COMMIT(); }
        if (c + 2 < 24) { CP_WAIT(1); } else { CP_WAIT(0); }   // stage c+1 complete
        // compute chunk c from f16 buf c&1 + B slot c%3 (both ready & visible)
        const uint32_t slotA = smb + SM_AF16 + (c & 1) * AF16_SZ;
        const uint32_t slotB = smb + SM_BQ + (c % 3) * BQ_SZ;
#pragma unroll
        for (int s = 0; s < 4; s++) {
            uint32_t a[2][4], bb[4][4];
#pragma unroll
            for (int mf = 0; mf < 2; mf++)
                LDSM_X4(a[mf], slotA + SW128(aBase + mf * 2048 + s * 32));
#pragma unroll
            for (int nb = 0; nb < 4; nb++)
                LDSM_X4(bb[nb], slotB + SW128(bBase + nb * 2048 + s * 32));
#pragma unroll
            for (int mf = 0; mf < 2; mf++)
#pragma unroll
                for (int nf = 0; nf < 8; nf++) {
                    const int nb = nf >> 1, h = (nf & 1) * 2;
                    MMA16816(d[mf][nf], a[mf], bb[nb][h], bb[nb][h + 1]);
                }
        }
        __syncthreads();                   // all waits+LDSMs done -> A(c+1) visible, buf (c+1)&1 free
        if (c + 1 < 24) cvtA(c + 1);
        __syncthreads();                   // f16 buf (c+1)&1 visible for next chunk
    }
    CP_WAIT(0);

    const int gid = ln >> 2, tc = (ln & 3) * 2;
#pragma unroll
    for (int nf = 0; nf < 8; nf++) {
        const int col = n0 + wn * 64 + nf * 8 + tc;
#pragma unroll
        for (int mf = 0; mf < 2; mf++) {
            const int r0 = m0 + wm * 32 + mf * 16 + gid;
            float* dd = d[mf][nf];
            float2 a0 = __ldg((const float2*)(g_agw + (size_t)(r0 / 10) * 512 + col));
            float2 a1 = __ldg((const float2*)(g_agw + (size_t)((r0 + 8) / 10) * 512 + col));
            __half2 h0 = __floats2half2_rn(fmaxf(dd[0] + a0.x, 0.0f), fmaxf(dd[1] + a0.y, 0.0f));
            __half2 h1 = __floats2half2_rn(fmaxf(dd[2] + a1.x, 0.0f), fmaxf(dd[3] + a1.y, 0.0f));
            *(__half2*)(g_embh + (size_t)r0 * 512 + col) = h0;
            *(__half2*)(g_embh + (size_t)(r0 + 8) * 512 + col) = h1;
        }
    }
}

// ---------------- Kernel 6: GEMM2 logits += emb[4096,5120] @ W2h^T --------------
#define G2_STAGES  4
#define G2_A_STAGE 16384
#define G2_B_STAGE 2048
#define G2_SMEM    (G2_STAGES * (G2_A_STAGE + G2_B_STAGE))  // 73728

__global__ void __launch_bounds__(256, 1) gemm2_kernel(float* __restrict__ logits) {
    extern __shared__ char sm[];
    const uint32_t sA = smem_u32(sm);
    const uint32_t sB = sA + G2_STAGES * G2_A_STAGE;
    const int t = threadIdx.x;
    const int m0 = blockIdx.x * 128;
    const int kbase = blockIdx.y * 640;
    const __half* gA = g_embh + (size_t)m0 * 5120 + kbase;
    const __half* gB = g_W2h + kbase;

    const int lrow = t >> 3, lcu = t & 7;
    const int warp = t >> 5, ln = t & 31;
    const int a_row = (ln & 7) + ((ln >> 3) & 1) * 8;
    const int a_kb  = (ln >> 4) << 4;
    const uint32_t aBase = (uint32_t)(warp * 16 + a_row) * 128 + a_kb;
    const int b_row = (ln & 7) + ((ln >> 4) << 3);
    const int b_kb  = ((ln >> 3) & 1) << 4;
    const uint32_t bBase = (uint32_t)b_row * 128 + b_kb;

    float d[2][4];
#pragma unroll
    for (int nf = 0; nf < 2; nf++)
#pragma unroll
        for (int q = 0; q < 4; q++) d[nf][q] = 0.0f;

    auto load_stage = [&](int c, int slot) {
        const int k0 = c * 64;
#pragma unroll
        for (int i = 0; i < 4; i++) {
            int row = lrow + 32 * i;
            CP16(sA + slot * G2_A_STAGE + SW128(row * 128 + lcu * 16),
                 gA + (size_t)row * 5120 + k0 + lcu * 8);
        }
        if (t < 128) {
            int row = t >> 3;
            CP16(sB + slot * G2_B_STAGE + SW128(row * 128 + lcu * 16),
                 gB + (size_t)row * 5120 + k0 + lcu * 8);
        }
    };

#pragma unroll
    for (int s = 0; s < G2_STAGES - 1; s++) { load_stage(s, s); CP_COMMIT(); }

    for (int c = 0; c < 10; c++) {
        CP_WAIT(2);
        __syncthreads();
        if (c + G2_STAGES - 1 < 10) load_stage(c + G2_STAGES - 1, (c + G2_STAGES - 1) & 3);
        CP_COMMIT();
        const uint32_t slotA = sA + (c & 3) * G2_A_STAGE;
        const uint32_t slotB = sB + (c & 3) * G2_B_STAGE;
#pragma unroll
        for (int s = 0; s < 4; s++) {
            uint32_t a[4], bb[4];
            LDSM_X4(a, slotA + SW128(aBase + s * 32));
            LDSM_X4(bb, slotB + SW128(bBase + s * 32));
            MMA16816(d[0], a, bb[0], bb[1]);
            MMA16816(d[1], a, bb[2], bb[3]);
        }
    }
    CP_WAIT(0);

    const int gid = ln >> 2, tc = (ln & 3) * 2;
#pragma unroll
    for (int nf = 0; nf < 2; nf++)
#pragma unroll
        for (int q = 0; q < 4; q++) {
            int col = nf * 8 + tc + (q & 1);
            int row = m0 + warp * 16 + gid + (q >> 1) * 8;
            if (col < 10) atomicAdd(&logits[(size_t)row * 10 + col], d[nf][q]);
        }
}

// ---------------- launch: strictly serial --------------------------------------
extern "C" void kernel_launch(void* const* d_in, const int* in_sizes, int n_in,
                              void* d_out, int out_size) {
    const float* agent = (const float*)d_in[0];
    const float* lanec = (const float*)d_in[1];
    const float* nghl  = (const float*)d_in[2];
    const float* ngh   = (const float*)d_in[3];
    const int*   label = (const int*)d_in[4];
    const float* W1    = (const float*)d_in[5];
    const float* b1    = (const float*)d_in[6];
    const float* W2    = (const float*)d_in[7];
    const float* b2    = (const float*)d_in[8];
    float* out = (float*)d_out;

    cudaFuncSetAttribute(agemm_kernel, cudaFuncAttributeMaxDynamicSharedMemorySize, AG_SMEM);
    cudaFuncSetAttribute(gemm1_kernel, cudaFuncAttributeMaxDynamicSharedMemorySize, G1_SMEM);
    cudaFuncSetAttribute(gemm2_kernel, cudaFuncAttributeMaxDynamicSharedMemorySize, G2_SMEM);

    w1t_kernel<<<dim3(64, 16), dim3(32, 8)>>>(W1);
    prep2_kernel<<<2528, 256>>>(agent, W2, b2, out);
    agemm_kernel<<<dim3(4, 32), 256, AG_SMEM>>>(b1);
    gather_kernel<<<4096, 128>>>(lanec, nghl, ngh, label, out);
    gemm1_kernel<<<dim3(2, 320), 512, G1_SMEM>>>(lanec, nghl, ngh);
    gemm2_kernel<<<dim3(32, 8), 256, G2_SMEM>>>(out);
}

// round 17
// speedup vs baseline: 1.3255x; 1.3255x over previous
#include <cuda_runtime.h>
#include <cuda_fp16.h>
#include <cstdint>
#include <cstddef>

// Problem: B=4096, P=10, LD=TD=512, DIN=2048, BP=40960
// out = [logits 4096x10][best_lane 4096x512][best_nghl 4096x512][best_ngh 4096x512]
// compute_103 PTX -> legacy mma.sync.m16n8k16 + cp.async only.
// ctx@W1 = agent@W1a (x10 smaller) + [lane|nghl|ngh]@W1bcd.
// R15 structure (verified best 264.2us). In-GEMM f32->f16 fusion tested 3x,
// always slower -> DRAM round-trip via prep_rows (84.8% HBM, at floor) is final.
// This round: w1t merged into prep kernel (one fewer launch), all else R15.

__device__ __align__(16) __half g_W1t[512 * 2048];       // W1^T fp16 [n][k]
__device__ __align__(16) __half g_laneh[40960u * 512];   // lane fp16
__device__ __align__(16) __half g_nghlh[40960u * 512];   // nghl fp16
__device__ __align__(16) __half g_nghh[40960u * 512];    // ngh fp16
__device__ __align__(16) __half g_agenth[4096u * 512];   // agent fp16
__device__ __align__(16) float  g_agw[4096u * 512];      // agent@W1a + b1 (fp32)
__device__ __align__(16) __half g_embh[40960u * 512];    // relu(...) fp16 (= [4096][5120])
__device__ __align__(16) __half g_W2h[16 * 5120];        // W2^T padded fp16 [n16][k5120]

#define SW128(o) ((o) ^ (((o) >> 3) & 0x70))

__device__ __forceinline__ uint32_t smem_u32(const void* p) {
    uint32_t a;
    asm("{ .reg .u64 t; cvta.to.shared.u64 t, %1; cvt.u32.u64 %0, t; }" : "=r"(a) : "l"(p));
    return a;
}
__device__ __forceinline__ uint32_t pack_h2(float a, float b) {
    __half2 h = __floats2half2_rn(a, b);
    return *reinterpret_cast<uint32_t*>(&h);
}

#define CP16(dst, src) \
    asm volatile("cp.async.cg.shared.global [%0], [%1], 16;" :: "r"(dst), "l"(src) : "memory")
#define CP_COMMIT() asm volatile("cp.async.commit_group;" ::: "memory")
#define CP_WAIT(n)  asm volatile("cp.async.wait_group %0;" :: "n"(n) : "memory")

#define LDSM_X4(r, addr)                                                          \
    asm volatile("ldmatrix.sync.aligned.m8n8.x4.shared.b16 {%0,%1,%2,%3}, [%4];"  \
        : "=r"((r)[0]), "=r"((r)[1]), "=r"((r)[2]), "=r"((r)[3]) : "r"(addr))

#define MMA16816(d, a, b0, b1)                                                    \
    asm volatile("mma.sync.aligned.m16n8k16.row.col.f32.f16.f16.f32 "             \
        "{%0,%1,%2,%3}, {%4,%5,%6,%7}, {%8,%9}, {%0,%1,%2,%3};"                    \
        : "+f"((d)[0]), "+f"((d)[1]), "+f"((d)[2]), "+f"((d)[3])                   \
        : "r"((a)[0]), "r"((a)[1]), "r"((a)[2]), "r"((a)[3]), "r"(b0), "r"(b1))

// ---------------- Kernel 1 (merged): W1 transpose + agent cvt + W2 cvt + logits init
// blocks [0,1024):      W1[2048,512] f32 -> W1t[512][2048] f16 (32x32 tiles)
// blocks [1024,3072):   agent f32->f16 (float4 granularity)
// blocks [3072,3552):   W2 -> fp16 padded (81920) then logits = b2 (40960)
__global__ void __launch_bounds__(256) prep_kernel(const float* __restrict__ W1,
                                                   const float* __restrict__ agent,
                                                   const float* __restrict__ W2,
                                                   const float* __restrict__ b2,
                                                   float* __restrict__ logits) {
    __shared__ float ts[32][33];
    int blk = blockIdx.x;
    if (blk < 1024) {
        int kk = (blk & 63) * 32, nn = (blk >> 6) * 32;
        int tx = threadIdx.x & 31, ty = threadIdx.x >> 5;  // 32 x 8
#pragma unroll
        for (int q = 0; q < 4; q++)
            ts[ty + 8 * q][tx] = W1[(size_t)(kk + ty + 8 * q) * 512 + nn + tx];
        __syncthreads();
#pragma unroll
        for (int q = 0; q < 4; q++)
            g_W1t[(size_t)(nn + ty + 8 * q) * 2048 + kk + tx] = __float2half(ts[tx][ty + 8 * q]);
    } else if (blk < 3072) {
        int idx = (blk - 1024) * 256 + threadIdx.x;  // 524288 float4s
        float4 v = __ldg((const float4*)agent + idx);
        uint2 o = { pack_h2(v.x, v.y), pack_h2(v.z, v.w) };
        *(uint2*)(g_agenth + (size_t)idx * 4) = o;
    } else {
        int idx = (blk - 3072) * 256 + threadIdx.x;  // 122880
        if (idx < 81920) {
            int n = idx / 5120, k = idx % 5120;
            g_W2h[idx] = __float2half(n < 10 ? W2[(size_t)k * 10 + n] : 0.0f);
        } else {
            int j = idx - 81920;                     // 40960
            logits[j] = __ldg(b2 + j % 10);
        }
    }
}

// ---------------- Kernel 2: lane/nghl/ngh f32->f16 + fused gather (2 rows/blk) -----
__global__ void __launch_bounds__(256) prep_rows_kernel(
    const float* __restrict__ lanec, const float* __restrict__ nghl,
    const float* __restrict__ ngh,
    const int* __restrict__ label,   float* __restrict__ out)
{
    const int row = blockIdx.x * 2 + (threadIdx.x >> 7);   // 0..40959
    const int t = threadIdx.x & 127;
    const size_t src = (size_t)row * 512 + t * 4;
    float4 v1 = __ldg((const float4*)(lanec + src));
    float4 v2 = __ldg((const float4*)(nghl + src));
    float4 v3 = __ldg((const float4*)(ngh + src));
    uint2 o1 = { pack_h2(v1.x, v1.y), pack_h2(v1.z, v1.w) };
    uint2 o2 = { pack_h2(v2.x, v2.y), pack_h2(v2.z, v2.w) };
    uint2 o3 = { pack_h2(v3.x, v3.y), pack_h2(v3.z, v3.w) };
    *(uint2*)(g_laneh + src) = o1;
    *(uint2*)(g_nghlh + src) = o2;
    *(uint2*)(g_nghh + src) = o3;
    if (__ldg(label + row) == 1) {         // fused gather (one row per batch)
        size_t b = row / 10;
        size_t dst = b * 512 + t * 4;
        *(float4*)(out + 40960 + dst) = v1;
        *(float4*)(out + 40960 + 2097152 + dst) = v2;
        *(float4*)(out + 40960 + 4194304 + dst) = v3;
    }
}

// ---------------- Kernel 3: agemm  g_agw = agent@W1a + b1 (fp32) ----------------
#define AG_STAGES  4
#define AG_A_STAGE 16384
#define AG_B_STAGE 16384
#define AG_SMEM    (AG_STAGES * (AG_A_STAGE + AG_B_STAGE))   // 131072

__global__ void __launch_bounds__(256, 1) agemm_kernel(const float* __restrict__ b1) {
    extern __shared__ char sm[];
    const uint32_t sA = smem_u32(sm);
    const uint32_t sB = sA + AG_STAGES * AG_A_STAGE;
    const int t = threadIdx.x;
    const int n0 = blockIdx.x * 128;
    const int m0 = blockIdx.y * 128;
    const __half* gA = g_agenth + (size_t)m0 * 512;
    const __half* gB = g_W1t + (size_t)n0 * 2048;   // k offset 0..511

    const int lrow = t >> 3, lcu = t & 7;
    const int warp = t >> 5, ln = t & 31;
    const int wm = warp & 3, wn = warp >> 2;
    const int a_row = (ln & 7) + ((ln >> 3) & 1) * 8;
    const int a_kb  = (ln >> 4) << 4;
    const uint32_t aBase = (uint32_t)(wm * 32 + a_row) * 128 + a_kb;
    const int b_row = (ln & 7) + ((ln >> 4) << 3);
    const int b_kb  = ((ln >> 3) & 1) << 4;
    const uint32_t bBase = (uint32_t)(wn * 64 + b_row) * 128 + b_kb;

    float d[2][8][4];
#pragma unroll
    for (int mf = 0; mf < 2; mf++)
#pragma unroll
        for (int nf = 0; nf < 8; nf++)
#pragma unroll
            for (int q = 0; q < 4; q++) d[mf][nf][q] = 0.0f;

    auto load_stage = [&](int c, int slot) {
        const int k0 = c * 64;
#pragma unroll
        for (int i = 0; i < 4; i++) {
            int row = lrow + 32 * i;
            CP16(sA + slot * AG_A_STAGE + SW128(row * 128 + lcu * 16),
                 gA + (size_t)row * 512 + k0 + lcu * 8);
            CP16(sB + slot * AG_B_STAGE + SW128(row * 128 + lcu * 16),
                 gB + (size_t)row * 2048 + k0 + lcu * 8);
        }
    };

#pragma unroll
    for (int s = 0; s < AG_STAGES - 1; s++) { load_stage(s, s); CP_COMMIT(); }

    for (int c = 0; c < 8; c++) {
        CP_WAIT(2);
        __syncthreads();
        if (c + AG_STAGES - 1 < 8) load_stage(c + AG_STAGES - 1, (c + AG_STAGES - 1) & 3);
        CP_COMMIT();
        const uint32_t slotA = sA + (c & 3) * AG_A_STAGE;
        const uint32_t slotB = sB + (c & 3) * AG_B_STAGE;
#pragma unroll
        for (int s = 0; s < 4; s++) {
            uint32_t a[2][4], bb[4][4];
#pragma unroll
            for (int mf = 0; mf < 2; mf++)
                LDSM_X4(a[mf], slotA + SW128(aBase + mf * 2048 + s * 32));
#pragma unroll
            for (int nb = 0; nb < 4; nb++)
                LDSM_X4(bb[nb], slotB + SW128(bBase + nb * 2048 + s * 32));
#pragma unroll
            for (int mf = 0; mf < 2; mf++)
#pragma unroll
                for (int nf = 0; nf < 8; nf++) {
                    const int nb = nf >> 1, h = (nf & 1) * 2;
                    MMA16816(d[mf][nf], a[mf], bb[nb][h], bb[nb][h + 1]);
                }
        }
    }
    CP_WAIT(0);

    const int gid = ln >> 2, tc = (ln & 3) * 2;
#pragma unroll
    for (int nf = 0; nf < 8; nf++) {
        const int col = n0 + wn * 64 + nf * 8 + tc;
        float2 bv = __ldg((const float2*)(b1 + col));
#pragma unroll
        for (int mf = 0; mf < 2; mf++) {
            const int r0 = m0 + wm * 32 + mf * 16 + gid;
            float* dd = d[mf][nf];
            float2 s0 = { dd[0] + bv.x, dd[1] + bv.y };
            float2 s1 = { dd[2] + bv.x, dd[3] + bv.y };
            *(float2*)(g_agw + (size_t)r0 * 512 + col) = s0;
            *(float2*)(g_agw + (size_t)(r0 + 8) * 512 + col) = s1;
        }
    }
}

// ---------------- GEMM1 tile config (128m x 256n, 16 warps / 512 threads) ---------
#define STAGES    4
#define A_STAGE   16384                    // 128 rows x 128B
#define B_STAGE   32768                    // 256 rows x 128B
#define G1_SMEM   (STAGES * (A_STAGE + B_STAGE))   // 196608

// ---------------- Kernel 4: GEMM1 emb = relu(agw[b] + [lane|nghl|ngh]@W1bcd) -------
__global__ void __launch_bounds__(512, 1) gemm1_kernel() {
    extern __shared__ char sm[];
    const uint32_t sA = smem_u32(sm);
    const uint32_t sB = sA + STAGES * A_STAGE;
    const int t = threadIdx.x;
    const int n0 = blockIdx.x * 256;
    const int m0 = blockIdx.y * 128;
    const __half* gB = g_W1t + (size_t)n0 * 2048 + 512;  // k range 512..2048

    const int lrow = t >> 3, lcu = t & 7;  // lrow 0..63
    const int warp = t >> 5, ln = t & 31;  // warp 0..15
    const int wm = warp & 3, wn = warp >> 2;
    const int a_row = (ln & 7) + ((ln >> 3) & 1) * 8;
    const int a_kb  = (ln >> 4) << 4;
    const uint32_t aBase = (uint32_t)(wm * 32 + a_row) * 128 + a_kb;
    const int b_row = (ln & 7) + ((ln >> 4) << 3);
    const int b_kb  = ((ln >> 3) & 1) << 4;
    const uint32_t bBase = (uint32_t)(wn * 64 + b_row) * 128 + b_kb;

    float d[2][8][4];
#pragma unroll
    for (int mf = 0; mf < 2; mf++)
#pragma unroll
        for (int nf = 0; nf < 8; nf++)
#pragma unroll
            for (int q = 0; q < 4; q++) d[mf][nf][q] = 0.0f;

    auto load_stage = [&](int c, int slot) {
        const __half* gA;
        if (c < 8)       gA = g_laneh + (size_t)m0 * 512;
        else if (c < 16) gA = g_nghlh + (size_t)m0 * 512;
        else             gA = g_nghh + (size_t)m0 * 512;
        const int k0 = (c & 7) * 64;
#pragma unroll
        for (int i = 0; i < 2; i++) {
            int row = lrow + 64 * i;
            CP16(sA + slot * A_STAGE + SW128(row * 128 + lcu * 16),
                 gA + (size_t)row * 512 + k0 + lcu * 8);
        }
        const int kb0 = c * 64;
#pragma unroll
        for (int i = 0; i < 4; i++) {
            int row = lrow + 64 * i;
            CP16(sB + slot * B_STAGE + SW128(row * 128 + lcu * 16),
                 gB + (size_t)row * 2048 + kb0 + lcu * 8);
        }
    };

#pragma unroll
    for (int s = 0; s < STAGES - 1; s++) { load_stage(s, s); CP_COMMIT(); }

    for (int c = 0; c < 24; c++) {
        CP_WAIT(2);
        __syncthreads();
        if (c + STAGES - 1 < 24) load_stage(c + STAGES - 1, (c + STAGES - 1) & 3);
        CP_COMMIT();
        const uint32_t slotA = sA + (c & 3) * A_STAGE;
        const uint32_t slotB = sB + (c & 3) * B_STAGE;
#pragma unroll
        for (int s = 0; s < 4; s++) {
            uint32_t a[2][4], bb[4][4];
#pragma unroll
            for (int mf = 0; mf < 2; mf++)
                LDSM_X4(a[mf], slotA + SW128(aBase + mf * 2048 + s * 32));
#pragma unroll
            for (int nb = 0; nb < 4; nb++)
                LDSM_X4(bb[nb], slotB + SW128(bBase + nb * 2048 + s * 32));
#pragma unroll
            for (int mf = 0; mf < 2; mf++)
#pragma unroll
                for (int nf = 0; nf < 8; nf++) {
                    const int nb = nf >> 1, h = (nf & 1) * 2;
                    MMA16816(d[mf][nf], a[mf], bb[nb][h], bb[nb][h + 1]);
                }
        }
    }
    CP_WAIT(0);

    const int gid = ln >> 2, tc = (ln & 3) * 2;
#pragma unroll
    for (int nf = 0; nf < 8; nf++) {
        const int col = n0 + wn * 64 + nf * 8 + tc;
#pragma unroll
        for (int mf = 0; mf < 2; mf++) {
            const int r0 = m0 + wm * 32 + mf * 16 + gid;
            float* dd = d[mf][nf];
            float2 a0 = __ldg((const float2*)(g_agw + (size_t)(r0 / 10) * 512 + col));
            float2 a1 = __ldg((const float2*)(g_agw + (size_t)((r0 + 8) / 10) * 512 + col));
            __half2 h0 = __floats2half2_rn(fmaxf(dd[0] + a0.x, 0.0f), fmaxf(dd[1] + a0.y, 0.0f));
            __half2 h1 = __floats2half2_rn(fmaxf(dd[2] + a1.x, 0.0f), fmaxf(dd[3] + a1.y, 0.0f));
            *(__half2*)(g_embh + (size_t)r0 * 512 + col) = h0;
            *(__half2*)(g_embh + (size_t)(r0 + 8) * 512 + col) = h1;
        }
    }
}

// ---------------- Kernel 5: GEMM2 logits += emb[4096,5120] @ W2h^T --------------
#define G2_STAGES  4
#define G2_A_STAGE 16384
#define G2_B_STAGE 2048
#define G2_SMEM    (G2_STAGES * (G2_A_STAGE + G2_B_STAGE))  // 73728

__global__ void __launch_bounds__(256, 1) gemm2_kernel(float* __restrict__ logits) {
    extern __shared__ char sm[];
    const uint32_t sA = smem_u32(sm);
    const uint32_t sB = sA + G2_STAGES * G2_A_STAGE;
    const int t = threadIdx.x;
    const int m0 = blockIdx.x * 128;
    const int kbase = blockIdx.y * 640;
    const __half* gA = g_embh + (size_t)m0 * 5120 + kbase;
    const __half* gB = g_W2h + kbase;

    const int lrow = t >> 3, lcu = t & 7;
    const int warp = t >> 5, ln = t & 31;
    const int a_row = (ln & 7) + ((ln >> 3) & 1) * 8;
    const int a_kb  = (ln >> 4) << 4;
    const uint32_t aBase = (uint32_t)(warp * 16 + a_row) * 128 + a_kb;
    const int b_row = (ln & 7) + ((ln >> 4) << 3);
    const int b_kb  = ((ln >> 3) & 1) << 4;
    const uint32_t bBase = (uint32_t)b_row * 128 + b_kb;

    float d[2][4];
#pragma unroll
    for (int nf = 0; nf < 2; nf++)
#pragma unroll
        for (int q = 0; q < 4; q++) d[nf][q] = 0.0f;

    auto load_stage = [&](int c, int slot) {
        const int k0 = c * 64;
#pragma unroll
        for (int i = 0; i < 4; i++) {
            int row = lrow + 32 * i;
            CP16(sA + slot * G2_A_STAGE + SW128(row * 128 + lcu * 16),
                 gA + (size_t)row * 5120 + k0 + lcu * 8);
        }
        if (t < 128) {
            int row = t >> 3;
            CP16(sB + slot * G2_B_STAGE + SW128(row * 128 + lcu * 16),
                 gB + (size_t)row * 5120 + k0 + lcu * 8);
        }
    };

#pragma unroll
    for (int s = 0; s < G2_STAGES - 1; s++) { load_stage(s, s); CP_COMMIT(); }

    for (int c = 0; c < 10; c++) {
        CP_WAIT(2);
        __syncthreads();
        if (c + G2_STAGES - 1 < 10) load_stage(c + G2_STAGES - 1, (c + G2_STAGES - 1) & 3);
        CP_COMMIT();
        const uint32_t slotA = sA + (c & 3) * G2_A_STAGE;
        const uint32_t slotB = sB + (c & 3) * G2_B_STAGE;
#pragma unroll
        for (int s = 0; s < 4; s++) {
            uint32_t a[4], bb[4];
            LDSM_X4(a, slotA + SW128(aBase + s * 32));
            LDSM_X4(bb, slotB + SW128(bBase + s * 32));
            MMA16816(d[0], a, bb[0], bb[1]);
            MMA16816(d[1], a, bb[2], bb[3]);
        }
    }
    CP_WAIT(0);

    const int gid = ln >> 2, tc = (ln & 3) * 2;
#pragma unroll
    for (int nf = 0; nf < 2; nf++)
#pragma unroll
        for (int q = 0; q < 4; q++) {
            int col = nf * 8 + tc + (q & 1);
            int row = m0 + warp * 16 + gid + (q >> 1) * 8;
            if (col < 10) atomicAdd(&logits[(size_t)row * 10 + col], d[nf][q]);
        }
}

// ---------------- launch: strictly serial --------------------------------------
extern "C" void kernel_launch(void* const* d_in, const int* in_sizes, int n_in,
                              void* d_out, int out_size) {
    const float* agent = (const float*)d_in[0];
    const float* lanec = (const float*)d_in[1];
    const float* nghl  = (const float*)d_in[2];
    const float* ngh   = (const float*)d_in[3];
    const int*   label = (const int*)d_in[4];
    const float* W1    = (const float*)d_in[5];
    const float* b1    = (const float*)d_in[6];
    const float* W2    = (const float*)d_in[7];
    const float* b2    = (const float*)d_in[8];
    float* out = (float*)d_out;

    cudaFuncSetAttribute(agemm_kernel, cudaFuncAttributeMaxDynamicSharedMemorySize, AG_SMEM);
    cudaFuncSetAttribute(gemm1_kernel, cudaFuncAttributeMaxDynamicSharedMemorySize, G1_SMEM);
    cudaFuncSetAttribute(gemm2_kernel, cudaFuncAttributeMaxDynamicSharedMemorySize, G2_SMEM);

    prep_kernel<<<3552, 256>>>(W1, agent, W2, b2, out);
    agemm_kernel<<<dim3(4, 32), 256, AG_SMEM>>>(b1);
    prep_rows_kernel<<<20480, 256>>>(lanec, nghl, ngh, label, out);
    gemm1_kernel<<<dim3(2, 320), 512, G1_SMEM>>>();
    gemm2_kernel<<<dim3(32, 8), 256, G2_SMEM>>>(out);
}